// round 1
// baseline (speedup 1.0000x reference)
#include <cuda_runtime.h>
#include <cuda_bf16.h>

// Problem constants
#define B_TOT   4096
#define T_      64
#define D_      250
#define K_      1000     // (3 stack + 1 buffer) * D
#define H_      125
#define NT      4
#define NL      50

// Tiling
#define BM      32
#define BK      40
#define BN      256      // cols 0..124 = t-hidden, 128..252 = r-hidden, rest pad
#define THREADS 256
#define XS_STRIDE 1008   // padded row stride for X tile

#define SMEM_FLOATS (BM*XS_STRIDE + BK*BN)
#define SMEM_BYTES  (SMEM_FLOATS * 4)

__global__ __launch_bounds__(THREADS, 1)
void fused_parser_kernel(const float* __restrict__ lstm_out,
                         const int*   __restrict__ stack_index,
                         const int*   __restrict__ stack_len,
                         const int*   __restrict__ buffer_index,
                         const int*   __restrict__ buffer_len,
                         const float* __restrict__ W1t,
                         const float* __restrict__ b1t,
                         const float* __restrict__ W2t,
                         const float* __restrict__ b2t,
                         const float* __restrict__ W1r,
                         const float* __restrict__ b1r,
                         const float* __restrict__ W2r,
                         const float* __restrict__ b2r,
                         float* __restrict__ out)
{
    extern __shared__ float smem[];
    float* Xs = smem;                       // [BM][XS_STRIDE]
    float* Ws = smem + BM * XS_STRIDE;      // [BK][BN]  (reused as Hs [BM][256] in epilogue)
    int*   soff = (int*)Ws;                 // [BM][4]   (only live during gather phase)

    const int tid = threadIdx.x;
    const int b0  = blockIdx.x * BM;

    // ---- Phase 0: per-(row,slot) gather offsets ----
    if (tid < BM * 4) {
        int row = tid >> 2, s = tid & 3;
        int b = b0 + row;
        int t, valid;
        if (s < 3) { valid = (s < stack_len[b]);  t = stack_index[b * 3 + s]; }
        else       { valid = (0 < buffer_len[b]); t = buffer_index[b]; }
        soff[tid] = valid ? (b * T_ + t) * D_ : -1;
    }
    __syncthreads();

    // ---- Phase 1: gather X tile [BM][1000] into smem (float2 granularity) ----
    for (int idx = tid; idx < BM * 4 * 125; idx += THREADS) {
        int row = idx / 500;
        int rem = idx - row * 500;
        int s   = rem / 125;
        int d2  = rem - s * 125;
        int off = soff[row * 4 + s];
        float2 v = make_float2(0.f, 0.f);
        if (off >= 0) v = *(const float2*)(lstm_out + off + d2 * 2);
        *(float2*)(Xs + row * XS_STRIDE + s * D_ + d2 * 2) = v;
    }
    __syncthreads();

    // ---- Phase 2: layer-1 GEMM, BM=32 x BN=256, K tiled by 40 ----
    const int c  = tid & 31;     // col group: cols [c*4, c*4+3] and [128+c*4, 128+c*4+3]
    const int r4 = tid >> 5;     // row group: rows [r4*4, r4*4+3]

    // per-thread W source column pointer (combined layout)
    const float* wp = nullptr;
    if (tid < 125)                       wp = W1t + tid;
    else if (tid >= 128 && tid < 253)    wp = W1r + (tid - 128);

    float acc[4][8];
    #pragma unroll
    for (int i = 0; i < 4; ++i)
        #pragma unroll
        for (int j = 0; j < 8; ++j) acc[i][j] = 0.f;

    for (int kt = 0; kt < K_ / BK; ++kt) {
        const int k0 = kt * BK;
        __syncthreads();
        // load W tile [BK][BN]; lane tid = column index (coalesced along n)
        #pragma unroll
        for (int kk = 0; kk < BK; ++kk) {
            Ws[kk * BN + tid] = wp ? __ldg(wp + (k0 + kk) * H_) : 0.f;
        }
        __syncthreads();

        #pragma unroll
        for (int kk = 0; kk < BK; kk += 4) {
            float xr[4][4];
            #pragma unroll
            for (int i = 0; i < 4; ++i) {
                float4 v = *(const float4*)(Xs + (r4 * 4 + i) * XS_STRIDE + k0 + kk);
                xr[i][0] = v.x; xr[i][1] = v.y; xr[i][2] = v.z; xr[i][3] = v.w;
            }
            #pragma unroll
            for (int j = 0; j < 4; ++j) {
                float4 wb0 = *(const float4*)(Ws + (kk + j) * BN + c * 4);
                float4 wb1 = *(const float4*)(Ws + (kk + j) * BN + 128 + c * 4);
                #pragma unroll
                for (int i = 0; i < 4; ++i) {
                    float x = xr[i][j];
                    acc[i][0] += x * wb0.x;  acc[i][1] += x * wb0.y;
                    acc[i][2] += x * wb0.z;  acc[i][3] += x * wb0.w;
                    acc[i][4] += x * wb1.x;  acc[i][5] += x * wb1.y;
                    acc[i][6] += x * wb1.z;  acc[i][7] += x * wb1.w;
                }
            }
        }
    }

    // ---- Phase 3: bias + tanh, stage hidden into smem (reuse Ws region) ----
    __syncthreads();   // everyone done reading Ws
    float* Hs = Ws;    // [BM][256]
    {
        float bt[4], br[4];
        #pragma unroll
        for (int j = 0; j < 4; ++j) {
            int n = c * 4 + j;
            bt[j] = (n < 125) ? b1t[n] : 0.f;
            br[j] = (n < 125) ? b1r[n] : 0.f;
        }
        #pragma unroll
        for (int i = 0; i < 4; ++i) {
            int row = r4 * 4 + i;
            #pragma unroll
            for (int j = 0; j < 4; ++j) {
                Hs[row * 256 + c * 4 + j]       = tanhf(acc[i][j]     + bt[j]);
                Hs[row * 256 + 128 + c * 4 + j] = tanhf(acc[i][4 + j] + br[j]);
            }
        }
    }
    __syncthreads();

    // ---- Phase 4: tiny layer 2 + final tanh, write outputs ----
    for (int idx = tid; idx < BM * (NT + NL); idx += THREADS) {
        int row = idx / (NT + NL);
        int o   = idx - row * (NT + NL);
        const float* hrow = Hs + row * 256;
        int b = b0 + row;
        if (o < NT) {
            float s = b2t[o];
            #pragma unroll 5
            for (int k = 0; k < H_; ++k) s += hrow[k] * __ldg(W2t + k * NT + o);
            out[b * NT + o] = tanhf(s);
        } else {
            int oo = o - NT;
            float s = b2r[oo];
            #pragma unroll 5
            for (int k = 0; k < H_; ++k) s += hrow[128 + k] * __ldg(W2r + k * NL + oo);
            out[B_TOT * NT + b * NL + oo] = tanhf(s);
        }
    }
}

extern "C" void kernel_launch(void* const* d_in, const int* in_sizes, int n_in,
                              void* d_out, int out_size)
{
    const float* lstm_out     = (const float*)d_in[0];
    const int*   stack_index  = (const int*)  d_in[1];
    const int*   stack_len    = (const int*)  d_in[2];
    const int*   buffer_index = (const int*)  d_in[3];
    const int*   buffer_len   = (const int*)  d_in[4];
    const float* W1t          = (const float*)d_in[5];
    const float* b1t          = (const float*)d_in[6];
    const float* W2t          = (const float*)d_in[7];
    const float* b2t          = (const float*)d_in[8];
    const float* W1r          = (const float*)d_in[9];
    const float* b1r          = (const float*)d_in[10];
    const float* W2r          = (const float*)d_in[11];
    const float* b2r          = (const float*)d_in[12];
    float* out = (float*)d_out;

    cudaFuncSetAttribute(fused_parser_kernel,
                         cudaFuncAttributeMaxDynamicSharedMemorySize, SMEM_BYTES);

    fused_parser_kernel<<<B_TOT / BM, THREADS, SMEM_BYTES>>>(
        lstm_out, stack_index, stack_len, buffer_index, buffer_len,
        W1t, b1t, W2t, b2t, W1r, b1r, W2r, b2r, out);
}